// round 8
// baseline (speedup 1.0000x reference)
#include <cuda_runtime.h>
#include <cuda_fp16.h>
#include <mma.h>
#include <cstdint>

using namespace nvcuda;

#define BB 32
#define SS 2048
#define DD 1024
#define MM (BB * SS)

// ---------------- scratch (static device globals; no runtime alloc) ------
__device__ float  g_scores[BB * SS];
__device__ float  g_uq[BB * DD];
__device__ __half g_Whi[DD * DD];
__device__ __half g_Wlo[DD * DD];          // unscaled residual (subnormals ok)
__device__ __half g_Ahi[(size_t)MM * DD];
__device__ __half g_Alo[(size_t)MM * DD];

// ---------------- cp.async helpers ---------------------------------------
__device__ __forceinline__ uint32_t smem_u32(const void* p) {
    uint32_t a;
    asm("{ .reg .u64 t; cvta.to.shared.u64 t, %1; cvt.u32.u64 %0, t; }"
        : "=r"(a) : "l"(p));
    return a;
}
__device__ __forceinline__ void cp16(uint32_t dst, const void* src) {
    asm volatile("cp.async.cg.shared.global [%0], [%1], 16;" :: "r"(dst), "l"(src) : "memory");
}
__device__ __forceinline__ void cp_commit() {
    asm volatile("cp.async.commit_group;" ::: "memory");
}
template <int N> __device__ __forceinline__ void cp_wait() {
    asm volatile("cp.async.wait_group %0;" :: "n"(N) : "memory");
}

// ---------------- K_a: split W -> Whi/Wlo --------------------------------
__global__ void __launch_bounds__(256) wsplit_kernel(const float* __restrict__ W) {
    int i = (blockIdx.x * 256 + threadIdx.x) * 4;
    float4 v = *(const float4*)(W + i);
    __half2 h01 = __floats2half2_rn(v.x, v.y);
    __half2 h23 = __floats2half2_rn(v.z, v.w);
    float2 b01 = __half22float2(h01), b23 = __half22float2(h23);
    __half2 l01 = __floats2half2_rn(v.x - b01.x, v.y - b01.y);
    __half2 l23 = __floats2half2_rn(v.z - b23.x, v.w - b23.y);
    *(__half2*)(g_Whi + i)     = h01;
    *(__half2*)(g_Whi + i + 2) = h23;
    *(__half2*)(g_Wlo + i)     = l01;
    *(__half2*)(g_Wlo + i + 2) = l23;
}

// ---------------- K_a2: split h -> Ahi/Alo --------------------------------
__global__ void __launch_bounds__(256) asplit_kernel(const float* __restrict__ h) {
    size_t i = ((size_t)blockIdx.x * 256 + threadIdx.x) * 4;
    float4 v = *(const float4*)(h + i);
    __half2 h01 = __floats2half2_rn(v.x, v.y);
    __half2 h23 = __floats2half2_rn(v.z, v.w);
    float2 b01 = __half22float2(h01), b23 = __half22float2(h23);
    __half2 l01 = __floats2half2_rn(v.x - b01.x, v.y - b01.y);
    __half2 l23 = __floats2half2_rn(v.z - b23.x, v.w - b23.y);
    *(__half2*)(g_Ahi + i)     = h01;
    *(__half2*)(g_Ahi + i + 2) = h23;
    *(__half2*)(g_Alo + i)     = l01;
    *(__half2*)(g_Alo + i + 2) = l23;
}

// ---------------- K_b: uq = rs @ U^T; zero scores + matched --------------
__global__ void __launch_bounds__(256) init_kernel(const float* __restrict__ U,
                                                   const float* __restrict__ rs,
                                                   float* __restrict__ out) {
    int gtid = blockIdx.x * 256 + threadIdx.x;
    if (gtid < BB * SS) g_scores[gtid] = 0.0f;
    if (gtid < BB * DD) out[gtid] = 0.0f;

    int w = gtid >> 5;
    int lane = gtid & 31;
    if (w < BB * DD) {
        int b = w >> 10;
        int d = w & 1023;
        const float* Urow = U + (size_t)d * DD;
        const float* rb = rs + (size_t)b * DD;
        float acc = 0.0f;
        #pragma unroll 8
        for (int e = lane; e < DD; e += 32) acc += Urow[e] * rb[e];
        #pragma unroll
        for (int o = 16; o > 0; o >>= 1) acc += __shfl_xor_sync(0xffffffffu, acc, o);
        if (lane == 0) g_uq[w] = acc;
    }
}

// ---------------- K_c: fp16x3 GEMM + relu + score ------------------------
// Block tile 256m x 128n, BK=64, double-buffered cp.async.
// 8 warps = 4(m) x 2(n); warp tile 64m x 64n.
// Inner loop: B fragments live per ks, A streamed 2-at-a-time (low reg pressure).
#define LDH 72                    // halves; 144B row stride
#define A_TILE_B (256 * LDH * 2)  // 36864 B per A array
#define B_TILE_B (128 * LDH * 2)  // 18432 B per B array
#define STAGE_B (2 * A_TILE_B + 2 * B_TILE_B)   // 110592 B
#define SMEM_DYN (2 * STAGE_B)                  // 221184 B

__device__ __forceinline__ void load_stage(uint32_t st, int m0, int n0, int k0, int tid) {
    #pragma unroll
    for (int it = 0; it < 24; it++) {
        const int idx = tid + it * 256;
        const __half* src;
        uint32_t dst;
        if (it < 16) {
            const int rem = idx & 2047;         // A: 256 rows x 8 segs
            const int row = rem >> 3;
            const int seg = rem & 7;
            src = (it < 8 ? g_Ahi : g_Alo) + (size_t)(m0 + row) * DD + k0 + seg * 8;
            dst = st + (it < 8 ? 0 : A_TILE_B) + row * (LDH * 2) + seg * 16;
        } else {
            const int rem = idx & 1023;         // B: 128 rows x 8 segs
            const int row = rem >> 3;
            const int seg = rem & 7;
            src = (it < 20 ? g_Whi : g_Wlo) + (size_t)(n0 + row) * DD + k0 + seg * 8;
            dst = st + 2 * A_TILE_B + (it < 20 ? 0 : B_TILE_B) + row * (LDH * 2) + seg * 16;
        }
        cp16(dst, src);
    }
}

__global__ void __launch_bounds__(256, 1) gemm_score_kernel(const float* __restrict__ rs) {
    extern __shared__ __align__(16) unsigned char dyn[];
    __shared__ float uqs[128], qs[128];

    const int tid = threadIdx.x;
    const int wid = tid >> 5;
    const int wm  = wid & 3;     // 4 m-warps (64 rows each)
    const int wn  = wid >> 2;    // 2 n-warps (64 cols each)
    const int m0  = blockIdx.y * 256;
    const int n0  = blockIdx.x * 128;
    const int b   = blockIdx.y >> 3;   // 8 m-blocks per batch

    if (tid < 128) {
        uqs[tid] = g_uq[b * DD + n0 + tid];
        qs[tid]  = rs[(size_t)b * DD + n0 + tid];
    }

    const uint32_t sbase = smem_u32(dyn);

    wmma::fragment<wmma::accumulator, 16, 16, 16, float> acc[4][4];
    #pragma unroll
    for (int i = 0; i < 4; i++)
        #pragma unroll
        for (int j = 0; j < 4; j++)
            wmma::fill_fragment(acc[i][j], 0.0f);

    load_stage(sbase, m0, n0, 0, tid);
    cp_commit();

    #pragma unroll 1
    for (int s = 0; s < 16; s++) {
        cp_wait<0>();        // the single in-flight group (stage s) complete
        __syncthreads();     // stage s visible to all; prior reads of buf done

        const __half* Ahi = (const __half*)(dyn + (s & 1) * STAGE_B);
        const __half* Bhi = Ahi + 2 * 256 * LDH;

        #pragma unroll
        for (int ks = 0; ks < 4; ks++) {
            // B fragments for this k-slice (8 LDSM, then they stay live)
            wmma::fragment<wmma::matrix_b, 16, 16, 16, __half, wmma::col_major> bh[4], bl[4];
            #pragma unroll
            for (int j = 0; j < 4; j++) {
                const __half* pb = Bhi + (wn * 64 + j * 16) * LDH + ks * 16;
                wmma::load_matrix_sync(bh[j], pb, LDH);
                wmma::load_matrix_sync(bl[j], pb + 128 * LDH, LDH);
            }
            // issue next stage's loads after the first LDSMs, off the barrier exit
            if (ks == 0 && s + 1 < 16) {
                load_stage(sbase + ((s + 1) & 1) * STAGE_B, m0, n0, (s + 1) * 64, tid);
                cp_commit();
            }
            // stream A 2 fragments at a time
            #pragma unroll
            for (int i = 0; i < 4; i++) {
                wmma::fragment<wmma::matrix_a, 16, 16, 16, __half, wmma::row_major> ah, al;
                const __half* pa = Ahi + (wm * 64 + i * 16) * LDH + ks * 16;
                wmma::load_matrix_sync(ah, pa, LDH);
                wmma::load_matrix_sync(al, pa + 256 * LDH, LDH);
                #pragma unroll
                for (int j = 0; j < 4; j++)
                    wmma::mma_sync(acc[i][j], ah, bh[j], acc[i][j]);   // hi*hi
                #pragma unroll
                for (int j = 0; j < 4; j++)
                    wmma::mma_sync(acc[i][j], ah, bl[j], acc[i][j]);   // hi*lo
                #pragma unroll
                for (int j = 0; j < 4; j++)
                    wmma::mma_sync(acc[i][j], al, bh[j], acc[i][j]);   // lo*hi
            }
        }
    }
    __syncthreads();   // all mma reads done before aliasing smem as Es

    // epilogue: stage acc to smem, relu(+uq)*q, row-reduce, atomicAdd
    float* Es = (float*)dyn;    // 256 x 132 fp32 = 135168 B
    #pragma unroll
    for (int i = 0; i < 4; i++)
        #pragma unroll
        for (int j = 0; j < 4; j++)
            wmma::store_matrix_sync(Es + (wm * 64 + i * 16) * 132 + (wn * 64 + j * 16),
                                    acc[i][j], 132, wmma::mem_row_major);
    __syncthreads();

    float partial = 0.0f;
    const float* row = Es + tid * 132;
    #pragma unroll 16
    for (int c = 0; c < 128; c++) {
        float v = row[c] + uqs[c];
        partial += fmaxf(v, 0.0f) * qs[c];
    }
    atomicAdd(&g_scores[m0 + tid], partial);
}

// ---------------- K_d: softmax over S per batch ---------------------------
__global__ void __launch_bounds__(256) softmax_kernel(float* __restrict__ out) {
    const int b = blockIdx.x;
    const int tid = threadIdx.x;
    __shared__ float red[256];
    const float* sc = g_scores + (size_t)b * SS;
    float* wout = out + BB * DD + (size_t)b * SS;

    float mx = -1e30f;
    for (int i = tid; i < SS; i += 256) mx = fmaxf(mx, sc[i]);
    red[tid] = mx; __syncthreads();
    for (int s = 128; s > 0; s >>= 1) {
        if (tid < s) red[tid] = fmaxf(red[tid], red[tid + s]);
        __syncthreads();
    }
    mx = red[0]; __syncthreads();

    float sum = 0.0f;
    for (int i = tid; i < SS; i += 256) {
        float e = expf(sc[i] - mx);
        wout[i] = e;
        sum += e;
    }
    red[tid] = sum; __syncthreads();
    for (int s = 128; s > 0; s >>= 1) {
        if (tid < s) red[tid] += red[tid + s];
        __syncthreads();
    }
    float inv = 1.0f / red[0];
    for (int i = tid; i < SS; i += 256) wout[i] *= inv;
}

// ---------------- K_e: matched[b,d] += sum_{s chunk} h*w ------------------
__global__ void __launch_bounds__(256) matched_kernel(const float* __restrict__ h,
                                                      float* __restrict__ out) {
    const int b  = blockIdx.y;
    const int sc = blockIdx.z;
    const int d  = blockIdx.x * 256 + threadIdx.x;
    __shared__ float ws[256];
    const float* w = out + BB * DD + (size_t)b * SS + sc * 256;
    ws[threadIdx.x] = w[threadIdx.x];
    __syncthreads();

    const float* hb = h + ((size_t)b * SS + sc * 256) * DD + d;
    float acc = 0.0f;
    #pragma unroll 8
    for (int s = 0; s < 256; s++) acc += hb[(size_t)s * DD] * ws[s];
    atomicAdd(&out[(size_t)b * DD + d], acc);
}

// ---------------------------------------------------------------------------
extern "C" void kernel_launch(void* const* d_in, const int* in_sizes, int n_in,
                              void* d_out, int out_size) {
    const float* h  = (const float*)d_in[0];
    const float* rs = (const float*)d_in[1];
    const float* W  = (const float*)d_in[2];
    const float* U  = (const float*)d_in[3];
    float* out = (float*)d_out;

    cudaFuncSetAttribute(gemm_score_kernel,
                         cudaFuncAttributeMaxDynamicSharedMemorySize, SMEM_DYN);

    wsplit_kernel<<<1024, 256>>>(W);
    asplit_kernel<<<65536, 256>>>(h);
    init_kernel<<<4096, 256>>>(U, rs, out);
    gemm_score_kernel<<<dim3(8, 256), 256, SMEM_DYN>>>(rs);
    softmax_kernel<<<BB, 256>>>(out);
    matched_kernel<<<dim3(DD / 256, BB, 8), 256>>>(h, out);
}

// round 9
// speedup vs baseline: 1.1154x; 1.1154x over previous
#include <cuda_runtime.h>
#include <cuda_fp16.h>
#include <mma.h>
#include <cstdint>

using namespace nvcuda;

#define BB 32
#define SS 2048
#define DD 1024
#define MM (BB * SS)

// ---------------- scratch (static device globals; no runtime alloc) ------
__device__ float  g_scores[BB * SS];
__device__ float  g_uq[BB * DD];
__device__ __half g_Whi[DD * DD];
__device__ __half g_Wlo[DD * DD];          // unscaled residual (subnormals ok)
__device__ __half g_Ahi[(size_t)MM * DD];
__device__ __half g_Alo[(size_t)MM * DD];

// ---------------- cp.async helpers ---------------------------------------
__device__ __forceinline__ uint32_t smem_u32(const void* p) {
    uint32_t a;
    asm("{ .reg .u64 t; cvta.to.shared.u64 t, %1; cvt.u32.u64 %0, t; }"
        : "=r"(a) : "l"(p));
    return a;
}
__device__ __forceinline__ void cp16(uint32_t dst, const void* src) {
    asm volatile("cp.async.cg.shared.global [%0], [%1], 16;" :: "r"(dst), "l"(src) : "memory");
}
__device__ __forceinline__ void cp_commit() {
    asm volatile("cp.async.commit_group;" ::: "memory");
}
template <int N> __device__ __forceinline__ void cp_wait() {
    asm volatile("cp.async.wait_group %0;" :: "n"(N) : "memory");
}

// ---------------- K_a: split W -> Whi/Wlo --------------------------------
__global__ void __launch_bounds__(256) wsplit_kernel(const float* __restrict__ W) {
    int i = (blockIdx.x * 256 + threadIdx.x) * 4;
    float4 v = *(const float4*)(W + i);
    __half2 h01 = __floats2half2_rn(v.x, v.y);
    __half2 h23 = __floats2half2_rn(v.z, v.w);
    float2 b01 = __half22float2(h01), b23 = __half22float2(h23);
    __half2 l01 = __floats2half2_rn(v.x - b01.x, v.y - b01.y);
    __half2 l23 = __floats2half2_rn(v.z - b23.x, v.w - b23.y);
    *(__half2*)(g_Whi + i)     = h01;
    *(__half2*)(g_Whi + i + 2) = h23;
    *(__half2*)(g_Wlo + i)     = l01;
    *(__half2*)(g_Wlo + i + 2) = l23;
}

// ---------------- K_a2: split h -> Ahi/Alo --------------------------------
__global__ void __launch_bounds__(256) asplit_kernel(const float* __restrict__ h) {
    size_t i = ((size_t)blockIdx.x * 256 + threadIdx.x) * 4;
    float4 v = *(const float4*)(h + i);
    __half2 h01 = __floats2half2_rn(v.x, v.y);
    __half2 h23 = __floats2half2_rn(v.z, v.w);
    float2 b01 = __half22float2(h01), b23 = __half22float2(h23);
    __half2 l01 = __floats2half2_rn(v.x - b01.x, v.y - b01.y);
    __half2 l23 = __floats2half2_rn(v.z - b23.x, v.w - b23.y);
    *(__half2*)(g_Ahi + i)     = h01;
    *(__half2*)(g_Ahi + i + 2) = h23;
    *(__half2*)(g_Alo + i)     = l01;
    *(__half2*)(g_Alo + i + 2) = l23;
}

// ---------------- K_b: uq = rs @ U^T; zero scores + matched --------------
__global__ void __launch_bounds__(256) init_kernel(const float* __restrict__ U,
                                                   const float* __restrict__ rs,
                                                   float* __restrict__ out) {
    int gtid = blockIdx.x * 256 + threadIdx.x;
    if (gtid < BB * SS) g_scores[gtid] = 0.0f;
    if (gtid < BB * DD) out[gtid] = 0.0f;

    int w = gtid >> 5;
    int lane = gtid & 31;
    if (w < BB * DD) {
        int b = w >> 10;
        int d = w & 1023;
        const float* Urow = U + (size_t)d * DD;
        const float* rb = rs + (size_t)b * DD;
        float acc = 0.0f;
        #pragma unroll 8
        for (int e = lane; e < DD; e += 32) acc += Urow[e] * rb[e];
        #pragma unroll
        for (int o = 16; o > 0; o >>= 1) acc += __shfl_xor_sync(0xffffffffu, acc, o);
        if (lane == 0) g_uq[w] = acc;
    }
}

// ---------------- K_c: fp16x3 GEMM + relu + score ------------------------
// Block tile 256m x 128n, BK=64, double-buffered cp.async.
// 8 warps = 4(m) x 2(n); warp tile 64m x 64n.
// cp.async for stage s+1 is SPREAD across the 16 MMA groups of stage s
// (2 copies per thread per group, groups 0..11) so LDGSTS issue interleaves
// with HMMA instead of bursting and starving the tensor pipe.
#define LDH 72                    // halves; 144B row stride
#define A_TILE_B (256 * LDH * 2)  // 36864 B per A array
#define B_TILE_B (128 * LDH * 2)  // 18432 B per B array
#define STAGE_B (2 * A_TILE_B + 2 * B_TILE_B)   // 110592 B
#define SMEM_DYN (2 * STAGE_B)                  // 221184 B

// one 16B copy, transfer index it in [0,24)
__device__ __forceinline__ void cp_piece(int it, uint32_t st, int m0, int n0, int k0, int tid) {
    const int idx = tid + it * 256;
    const __half* src;
    uint32_t dst;
    if (it < 16) {
        const int rem = idx & 2047;         // A: 256 rows x 8 segs
        const int row = rem >> 3;
        const int seg = rem & 7;
        src = (it < 8 ? g_Ahi : g_Alo) + (size_t)(m0 + row) * DD + k0 + seg * 8;
        dst = st + (it < 8 ? 0 : A_TILE_B) + row * (LDH * 2) + seg * 16;
    } else {
        const int rem = idx & 1023;         // B: 128 rows x 8 segs
        const int row = rem >> 3;
        const int seg = rem & 7;
        src = (it < 20 ? g_Whi : g_Wlo) + (size_t)(n0 + row) * DD + k0 + seg * 8;
        dst = st + 2 * A_TILE_B + (it < 20 ? 0 : B_TILE_B) + row * (LDH * 2) + seg * 16;
    }
    cp16(dst, src);
}

__device__ __forceinline__ void load_stage(uint32_t st, int m0, int n0, int k0, int tid) {
    #pragma unroll
    for (int it = 0; it < 24; it++) cp_piece(it, st, m0, n0, k0, tid);
}

__global__ void __launch_bounds__(256, 1) gemm_score_kernel(const float* __restrict__ rs) {
    extern __shared__ __align__(16) unsigned char dyn[];
    __shared__ float uqs[128], qs[128];

    const int tid = threadIdx.x;
    const int wid = tid >> 5;
    const int wm  = wid & 3;     // 4 m-warps (64 rows each)
    const int wn  = wid >> 2;    // 2 n-warps (64 cols each)
    const int m0  = blockIdx.y * 256;
    const int n0  = blockIdx.x * 128;
    const int b   = blockIdx.y >> 3;   // 8 m-blocks per batch

    if (tid < 128) {
        uqs[tid] = g_uq[b * DD + n0 + tid];
        qs[tid]  = rs[(size_t)b * DD + n0 + tid];
    }

    const uint32_t sbase = smem_u32(dyn);

    wmma::fragment<wmma::accumulator, 16, 16, 16, float> acc[4][4];
    #pragma unroll
    for (int i = 0; i < 4; i++)
        #pragma unroll
        for (int j = 0; j < 4; j++)
            wmma::fill_fragment(acc[i][j], 0.0f);

    load_stage(sbase, m0, n0, 0, tid);
    cp_commit();

    #pragma unroll 1
    for (int s = 0; s < 16; s++) {
        cp_wait<0>();        // stage s complete (committed mid-stage s-1)
        __syncthreads();     // visible to all; buf (s+1)&1 reads all retired

        const __half* Ahi = (const __half*)(dyn + (s & 1) * STAGE_B);
        const __half* Bhi = Ahi + 2 * 256 * LDH;
        const uint32_t nst = sbase + ((s + 1) & 1) * STAGE_B;
        const int nk0 = (s + 1) * 64;
        const bool more = (s + 1 < 16);

        #pragma unroll
        for (int ks = 0; ks < 4; ks++) {
            // B fragments for this k-slice stay live
            wmma::fragment<wmma::matrix_b, 16, 16, 16, __half, wmma::col_major> bh[4], bl[4];
            #pragma unroll
            for (int j = 0; j < 4; j++) {
                const __half* pb = Bhi + (wn * 64 + j * 16) * LDH + ks * 16;
                wmma::load_matrix_sync(bh[j], pb, LDH);
                wmma::load_matrix_sync(bl[j], pb + 128 * LDH, LDH);
            }
            #pragma unroll
            for (int i = 0; i < 4; i++) {
                const int g = ks * 4 + i;           // group 0..15 (compile-time)
                if (more && g < 12) {               // 2 copies per group, spread
                    cp_piece(2 * g,     nst, m0, n0, nk0, tid);
                    cp_piece(2 * g + 1, nst, m0, n0, nk0, tid);
                }
                wmma::fragment<wmma::matrix_a, 16, 16, 16, __half, wmma::row_major> ah, al;
                const __half* pa = Ahi + (wm * 64 + i * 16) * LDH + ks * 16;
                wmma::load_matrix_sync(ah, pa, LDH);
                wmma::load_matrix_sync(al, pa + 256 * LDH, LDH);
                #pragma unroll
                for (int j = 0; j < 4; j++)
                    wmma::mma_sync(acc[i][j], ah, bh[j], acc[i][j]);   // hi*hi
                #pragma unroll
                for (int j = 0; j < 4; j++)
                    wmma::mma_sync(acc[i][j], ah, bl[j], acc[i][j]);   // hi*lo
                #pragma unroll
                for (int j = 0; j < 4; j++)
                    wmma::mma_sync(acc[i][j], al, bh[j], acc[i][j]);   // lo*hi
                if (more && g == 11) cp_commit();   // all 24 issued; ~4 groups to land
            }
        }
    }
    __syncthreads();   // all mma reads done before aliasing smem as Es

    // epilogue: stage acc to smem, relu(+uq)*q, row-reduce, atomicAdd
    float* Es = (float*)dyn;    // 256 x 132 fp32 = 135168 B
    #pragma unroll
    for (int i = 0; i < 4; i++)
        #pragma unroll
        for (int j = 0; j < 4; j++)
            wmma::store_matrix_sync(Es + (wm * 64 + i * 16) * 132 + (wn * 64 + j * 16),
                                    acc[i][j], 132, wmma::mem_row_major);
    __syncthreads();

    float partial = 0.0f;
    const float* row = Es + tid * 132;
    #pragma unroll 16
    for (int c = 0; c < 128; c++) {
        float v = row[c] + uqs[c];
        partial += fmaxf(v, 0.0f) * qs[c];
    }
    atomicAdd(&g_scores[m0 + tid], partial);
}

// ---------------- K_d: softmax over S per batch ---------------------------
__global__ void __launch_bounds__(256) softmax_kernel(float* __restrict__ out) {
    const int b = blockIdx.x;
    const int tid = threadIdx.x;
    __shared__ float red[256];
    const float* sc = g_scores + (size_t)b * SS;
    float* wout = out + BB * DD + (size_t)b * SS;

    float mx = -1e30f;
    for (int i = tid; i < SS; i += 256) mx = fmaxf(mx, sc[i]);
    red[tid] = mx; __syncthreads();
    for (int s = 128; s > 0; s >>= 1) {
        if (tid < s) red[tid] = fmaxf(red[tid], red[tid + s]);
        __syncthreads();
    }
    mx = red[0]; __syncthreads();

    float sum = 0.0f;
    for (int i = tid; i < SS; i += 256) {
        float e = expf(sc[i] - mx);
        wout[i] = e;
        sum += e;
    }
    red[tid] = sum; __syncthreads();
    for (int s = 128; s > 0; s >>= 1) {
        if (tid < s) red[tid] += red[tid + s];
        __syncthreads();
    }
    float inv = 1.0f / red[0];
    for (int i = tid; i < SS; i += 256) wout[i] *= inv;
}

// ---------------- K_e: matched[b,d] += sum_{s chunk} h*w (float4) --------
__global__ void __launch_bounds__(256) matched_kernel(const float* __restrict__ h,
                                                      float* __restrict__ out) {
    const int b  = blockIdx.y;
    const int sc = blockIdx.z;              // 8 chunks of 256 over S
    const int tid = threadIdx.x;            // 256 threads x 4 cols = 1024
    __shared__ float ws[256];
    ws[tid] = out[BB * DD + (size_t)b * SS + sc * 256 + tid];
    __syncthreads();

    const float4* hb = (const float4*)(h + ((size_t)b * SS + sc * 256) * DD) + tid;
    float4 acc = make_float4(0.f, 0.f, 0.f, 0.f);
    #pragma unroll 8
    for (int s = 0; s < 256; s++) {
        float4 v = hb[(size_t)s * (DD / 4)];
        float w = ws[s];
        acc.x += v.x * w; acc.y += v.y * w; acc.z += v.z * w; acc.w += v.w * w;
    }
    float* o = out + (size_t)b * DD + tid * 4;
    atomicAdd(o + 0, acc.x);
    atomicAdd(o + 1, acc.y);
    atomicAdd(o + 2, acc.z);
    atomicAdd(o + 3, acc.w);
}

// ---------------------------------------------------------------------------
extern "C" void kernel_launch(void* const* d_in, const int* in_sizes, int n_in,
                              void* d_out, int out_size) {
    const float* h  = (const float*)d_in[0];
    const float* rs = (const float*)d_in[1];
    const float* W  = (const float*)d_in[2];
    const float* U  = (const float*)d_in[3];
    float* out = (float*)d_out;

    cudaFuncSetAttribute(gemm_score_kernel,
                         cudaFuncAttributeMaxDynamicSharedMemorySize, SMEM_DYN);

    wsplit_kernel<<<1024, 256>>>(W);
    asplit_kernel<<<65536, 256>>>(h);
    init_kernel<<<4096, 256>>>(U, rs, out);
    gemm_score_kernel<<<dim3(8, 256), 256, SMEM_DYN>>>(rs);
    softmax_kernel<<<BB, 256>>>(out);
    matched_kernel<<<dim3(1, BB, 8), 256>>>(h, out);
}

// round 10
// speedup vs baseline: 1.1544x; 1.0349x over previous
#include <cuda_runtime.h>
#include <cuda_fp16.h>
#include <mma.h>
#include <cstdint>

using namespace nvcuda;

#define BB 32
#define SS 2048
#define DD 1024
#define MM (BB * SS)

// ---------------- scratch (static device globals; no runtime alloc) ------
__device__ float  g_scores[BB * SS];
__device__ float  g_uq[BB * DD];
__device__ __half g_Whi[DD * DD];
__device__ __half g_Wlo[DD * DD];          // unscaled residual (subnormals ok)
__device__ __half g_Ahi[(size_t)MM * DD];
__device__ __half g_Alo[(size_t)MM * DD];

// ---------------- cp.async helpers ---------------------------------------
__device__ __forceinline__ uint32_t smem_u32(const void* p) {
    uint32_t a;
    asm("{ .reg .u64 t; cvta.to.shared.u64 t, %1; cvt.u32.u64 %0, t; }"
        : "=r"(a) : "l"(p));
    return a;
}
__device__ __forceinline__ void cp16(uint32_t dst, const void* src) {
    asm volatile("cp.async.cg.shared.global [%0], [%1], 16;" :: "r"(dst), "l"(src) : "memory");
}
__device__ __forceinline__ void cp_commit() {
    asm volatile("cp.async.commit_group;" ::: "memory");
}
template <int N> __device__ __forceinline__ void cp_wait() {
    asm volatile("cp.async.wait_group %0;" :: "n"(N) : "memory");
}

// ---------------- K_a: split W -> Whi/Wlo --------------------------------
__global__ void __launch_bounds__(256) wsplit_kernel(const float* __restrict__ W) {
    int i = (blockIdx.x * 256 + threadIdx.x) * 4;
    float4 v = *(const float4*)(W + i);
    __half2 h01 = __floats2half2_rn(v.x, v.y);
    __half2 h23 = __floats2half2_rn(v.z, v.w);
    float2 b01 = __half22float2(h01), b23 = __half22float2(h23);
    __half2 l01 = __floats2half2_rn(v.x - b01.x, v.y - b01.y);
    __half2 l23 = __floats2half2_rn(v.z - b23.x, v.w - b23.y);
    *(__half2*)(g_Whi + i)     = h01;
    *(__half2*)(g_Whi + i + 2) = h23;
    *(__half2*)(g_Wlo + i)     = l01;
    *(__half2*)(g_Wlo + i + 2) = l23;
}

// ---------------- K_a2: split h -> Ahi/Alo --------------------------------
__global__ void __launch_bounds__(256) asplit_kernel(const float* __restrict__ h) {
    size_t i = ((size_t)blockIdx.x * 256 + threadIdx.x) * 4;
    float4 v = *(const float4*)(h + i);
    __half2 h01 = __floats2half2_rn(v.x, v.y);
    __half2 h23 = __floats2half2_rn(v.z, v.w);
    float2 b01 = __half22float2(h01), b23 = __half22float2(h23);
    __half2 l01 = __floats2half2_rn(v.x - b01.x, v.y - b01.y);
    __half2 l23 = __floats2half2_rn(v.z - b23.x, v.w - b23.y);
    *(__half2*)(g_Ahi + i)     = h01;
    *(__half2*)(g_Ahi + i + 2) = h23;
    *(__half2*)(g_Alo + i)     = l01;
    *(__half2*)(g_Alo + i + 2) = l23;
}

// ---------------- K_b: uq = rs @ U^T; zero scores + matched --------------
__global__ void __launch_bounds__(256) init_kernel(const float* __restrict__ U,
                                                   const float* __restrict__ rs,
                                                   float* __restrict__ out) {
    int gtid = blockIdx.x * 256 + threadIdx.x;
    if (gtid < BB * SS) g_scores[gtid] = 0.0f;
    if (gtid < BB * DD) out[gtid] = 0.0f;

    int w = gtid >> 5;
    int lane = gtid & 31;
    if (w < BB * DD) {
        int b = w >> 10;
        int d = w & 1023;
        const float* Urow = U + (size_t)d * DD;
        const float* rb = rs + (size_t)b * DD;
        float acc = 0.0f;
        #pragma unroll 8
        for (int e = lane; e < DD; e += 32) acc += Urow[e] * rb[e];
        #pragma unroll
        for (int o = 16; o > 0; o >>= 1) acc += __shfl_xor_sync(0xffffffffu, acc, o);
        if (lane == 0) g_uq[w] = acc;
    }
}

// ---------------- K_c: fp16x3 GEMM + relu + score ------------------------
// Block tile 256m x 128n, BK=64, double-buffered cp.async.
// 8 warps = 4(m) x 2(n); warp tile 64m x 64n.
// cp.async for stage s+1 spread across MMA groups (2 pieces/group, g 0..11).
// Addressing: 4 incremental src pointers + 1 smem base per stage; every
// piece is a single LDGSTS with compile-time immediate displacement.
#define LDH 72                    // halves; 144B row stride
#define ROWB (LDH * 2)            // 144 bytes per row
#define A_TILE_B (256 * ROWB)     // 36864 B per A array
#define B_TILE_B (128 * ROWB)     // 18432 B per B array
#define STAGE_B (2 * A_TILE_B + 2 * B_TILE_B)   // 110592 B
#define SMEM_DYN (2 * STAGE_B)                  // 221184 B
#define PSTRIDE_B (32 * ROWB)     // dst displacement per piece: 4608 B
#define PSTRIDE_H (32 * DD)       // src displacement per piece: 32768 halves

// one 16B piece; `it` is always a compile-time constant at the call site,
// so displacement math folds into LDGSTS immediates.
__device__ __forceinline__ void cp_pc(int it, uint32_t dstA,
                                      const __half* sAhi, const __half* sAlo,
                                      const __half* sWhi, const __half* sWlo) {
    if (it < 8)
        cp16(dstA + it * PSTRIDE_B, sAhi + (size_t)it * PSTRIDE_H);
    else if (it < 16)
        cp16(dstA + A_TILE_B + (it - 8) * PSTRIDE_B, sAlo + (size_t)(it - 8) * PSTRIDE_H);
    else if (it < 20)
        cp16(dstA + 2 * A_TILE_B + (it - 16) * PSTRIDE_B, sWhi + (size_t)(it - 16) * PSTRIDE_H);
    else
        cp16(dstA + 2 * A_TILE_B + B_TILE_B + (it - 20) * PSTRIDE_B,
             sWlo + (size_t)(it - 20) * PSTRIDE_H);
}

__global__ void __launch_bounds__(256, 1) gemm_score_kernel(const float* __restrict__ rs) {
    extern __shared__ __align__(16) unsigned char dyn[];
    __shared__ float uqs[128], qs[128];

    const int tid = threadIdx.x;
    const int wid = tid >> 5;
    const int wm  = wid & 3;     // 4 m-warps (64 rows each)
    const int wn  = wid >> 2;    // 2 n-warps (64 cols each)
    const int m0  = blockIdx.y * 256;
    const int n0  = blockIdx.x * 128;
    const int b   = blockIdx.y >> 3;   // 8 m-blocks per batch

    if (tid < 128) {
        uqs[tid] = g_uq[b * DD + n0 + tid];
        qs[tid]  = rs[(size_t)b * DD + n0 + tid];
    }

    const uint32_t sbase = smem_u32(dyn);
    const int rowT = tid >> 3;                 // 0..31
    const int segT = tid & 7;                  // 0..7
    const uint32_t offT = rowT * ROWB + segT * 16;
    // per-thread base source pointers at k0 = 0
    const __half* pAhi = g_Ahi + (size_t)(m0 + rowT) * DD + segT * 8;
    const __half* pAlo = g_Alo + (size_t)(m0 + rowT) * DD + segT * 8;
    const __half* pWhi = g_Whi + (size_t)(n0 + rowT) * DD + segT * 8;
    const __half* pWlo = g_Wlo + (size_t)(n0 + rowT) * DD + segT * 8;

    wmma::fragment<wmma::accumulator, 16, 16, 16, float> acc[4][4];
    #pragma unroll
    for (int i = 0; i < 4; i++)
        #pragma unroll
        for (int j = 0; j < 4; j++)
            wmma::fill_fragment(acc[i][j], 0.0f);

    // preload stage 0
    {
        const uint32_t d0 = sbase + offT;
        #pragma unroll
        for (int it = 0; it < 24; it++) cp_pc(it, d0, pAhi, pAlo, pWhi, pWlo);
        cp_commit();
    }

    #pragma unroll 1
    for (int s = 0; s < 16; s++) {
        cp_wait<0>();        // stage s complete
        __syncthreads();     // visible to all; buf (s+1)&1 reads all retired

        const __half* Ahi = (const __half*)(dyn + (s & 1) * STAGE_B);
        const __half* Bhi = Ahi + 2 * 256 * LDH;

        // next-stage copy context (cheap: 4 pointer adds + 1 smem add)
        const int nk0 = (s + 1) * 64;
        const uint32_t ndst = sbase + ((s + 1) & 1) * STAGE_B + offT;
        const __half* nAhi = pAhi + nk0;
        const __half* nAlo = pAlo + nk0;
        const __half* nWhi = pWhi + nk0;
        const __half* nWlo = pWlo + nk0;
        const bool more = (s + 1 < 16);

        #pragma unroll
        for (int ks = 0; ks < 4; ks++) {
            wmma::fragment<wmma::matrix_b, 16, 16, 16, __half, wmma::col_major> bh[4], bl[4];
            #pragma unroll
            for (int j = 0; j < 4; j++) {
                const __half* pb = Bhi + (wn * 64 + j * 16) * LDH + ks * 16;
                wmma::load_matrix_sync(bh[j], pb, LDH);
                wmma::load_matrix_sync(bl[j], pb + 128 * LDH, LDH);
            }
            #pragma unroll
            for (int i = 0; i < 4; i++) {
                const int g = ks * 4 + i;           // group 0..15 (compile-time)
                if (more && g < 12) {               // 2 pieces per group, spread
                    cp_pc(2 * g,     ndst, nAhi, nAlo, nWhi, nWlo);
                    cp_pc(2 * g + 1, ndst, nAhi, nAlo, nWhi, nWlo);
                }
                wmma::fragment<wmma::matrix_a, 16, 16, 16, __half, wmma::row_major> ah, al;
                const __half* pa = Ahi + (wm * 64 + i * 16) * LDH + ks * 16;
                wmma::load_matrix_sync(ah, pa, LDH);
                wmma::load_matrix_sync(al, pa + 256 * LDH, LDH);
                #pragma unroll
                for (int j = 0; j < 4; j++)
                    wmma::mma_sync(acc[i][j], ah, bh[j], acc[i][j]);   // hi*hi
                #pragma unroll
                for (int j = 0; j < 4; j++)
                    wmma::mma_sync(acc[i][j], ah, bl[j], acc[i][j]);   // hi*lo
                #pragma unroll
                for (int j = 0; j < 4; j++)
                    wmma::mma_sync(acc[i][j], al, bh[j], acc[i][j]);   // lo*hi
                if (more && g == 11) cp_commit();
            }
        }
    }
    __syncthreads();   // all mma reads done before aliasing smem as Es

    // epilogue: stage acc to smem, relu(+uq)*q, row-reduce, atomicAdd
    float* Es = (float*)dyn;    // 256 x 132 fp32 = 135168 B
    #pragma unroll
    for (int i = 0; i < 4; i++)
        #pragma unroll
        for (int j = 0; j < 4; j++)
            wmma::store_matrix_sync(Es + (wm * 64 + i * 16) * 132 + (wn * 64 + j * 16),
                                    acc[i][j], 132, wmma::mem_row_major);
    __syncthreads();

    float partial = 0.0f;
    const float* row = Es + tid * 132;
    #pragma unroll 16
    for (int c = 0; c < 128; c++) {
        float v = row[c] + uqs[c];
        partial += fmaxf(v, 0.0f) * qs[c];
    }
    atomicAdd(&g_scores[m0 + tid], partial);
}

// ---------------- K_d: softmax over S per batch ---------------------------
__global__ void __launch_bounds__(256) softmax_kernel(float* __restrict__ out) {
    const int b = blockIdx.x;
    const int tid = threadIdx.x;
    __shared__ float red[256];
    const float* sc = g_scores + (size_t)b * SS;
    float* wout = out + BB * DD + (size_t)b * SS;

    float mx = -1e30f;
    for (int i = tid; i < SS; i += 256) mx = fmaxf(mx, sc[i]);
    red[tid] = mx; __syncthreads();
    for (int s = 128; s > 0; s >>= 1) {
        if (tid < s) red[tid] = fmaxf(red[tid], red[tid + s]);
        __syncthreads();
    }
    mx = red[0]; __syncthreads();

    float sum = 0.0f;
    for (int i = tid; i < SS; i += 256) {
        float e = expf(sc[i] - mx);
        wout[i] = e;
        sum += e;
    }
    red[tid] = sum; __syncthreads();
    for (int s = 128; s > 0; s >>= 1) {
        if (tid < s) red[tid] += red[tid + s];
        __syncthreads();
    }
    float inv = 1.0f / red[0];
    for (int i = tid; i < SS; i += 256) wout[i] *= inv;
}

// ---------------- K_e: matched[b,d] += sum_{s chunk} h*w (float4) --------
__global__ void __launch_bounds__(256) matched_kernel(const float* __restrict__ h,
                                                      float* __restrict__ out) {
    const int b  = blockIdx.y;
    const int sc = blockIdx.z;              // 8 chunks of 256 over S
    const int tid = threadIdx.x;            // 256 threads x 4 cols = 1024
    __shared__ float ws[256];
    ws[tid] = out[BB * DD + (size_t)b * SS + sc * 256 + tid];
    __syncthreads();

    const float4* hb = (const float4*)(h + ((size_t)b * SS + sc * 256) * DD) + tid;
    float4 acc = make_float4(0.f, 0.f, 0.f, 0.f);
    #pragma unroll 8
    for (int s = 0; s < 256; s++) {
        float4 v = hb[(size_t)s * (DD / 4)];
        float w = ws[s];
        acc.x += v.x * w; acc.y += v.y * w; acc.z += v.z * w; acc.w += v.w * w;
    }
    float* o = out + (size_t)b * DD + tid * 4;
    atomicAdd(o + 0, acc.x);
    atomicAdd(o + 1, acc.y);
    atomicAdd(o + 2, acc.z);
    atomicAdd(o + 3, acc.w);
}

// ---------------------------------------------------------------------------
extern "C" void kernel_launch(void* const* d_in, const int* in_sizes, int n_in,
                              void* d_out, int out_size) {
    const float* h  = (const float*)d_in[0];
    const float* rs = (const float*)d_in[1];
    const float* W  = (const float*)d_in[2];
    const float* U  = (const float*)d_in[3];
    float* out = (float*)d_out;

    cudaFuncSetAttribute(gemm_score_kernel,
                         cudaFuncAttributeMaxDynamicSharedMemorySize, SMEM_DYN);

    wsplit_kernel<<<1024, 256>>>(W);
    asplit_kernel<<<65536, 256>>>(h);
    init_kernel<<<4096, 256>>>(U, rs, out);
    gemm_score_kernel<<<dim3(8, 256), 256, SMEM_DYN>>>(rs);
    softmax_kernel<<<BB, 256>>>(out);
    matched_kernel<<<dim3(1, BB, 8), 256>>>(h, out);
}

// round 11
// speedup vs baseline: 1.2189x; 1.0559x over previous
#include <cuda_runtime.h>
#include <cuda_fp16.h>
#include <mma.h>
#include <cstdint>

using namespace nvcuda;

#define BB 32
#define SS 2048
#define DD 1024
#define MM (BB * SS)

// ---------------- scratch (static device globals; no runtime alloc) ------
__device__ float  g_scores[BB * SS];
__device__ float  g_uq[BB * DD];
__device__ __half g_Whi[DD * DD];
__device__ __half g_Wlo[DD * DD];          // unscaled residual (subnormals ok)
__device__ __half g_Ahi[(size_t)MM * DD];
__device__ __half g_Alo[(size_t)MM * DD];

// ---------------- cp.async helpers ---------------------------------------
__device__ __forceinline__ uint32_t smem_u32(const void* p) {
    uint32_t a;
    asm("{ .reg .u64 t; cvta.to.shared.u64 t, %1; cvt.u32.u64 %0, t; }"
        : "=r"(a) : "l"(p));
    return a;
}
__device__ __forceinline__ void cp16(uint32_t dst, const void* src) {
    asm volatile("cp.async.cg.shared.global [%0], [%1], 16;" :: "r"(dst), "l"(src) : "memory");
}
__device__ __forceinline__ void cp_commit() {
    asm volatile("cp.async.commit_group;" ::: "memory");
}
template <int N> __device__ __forceinline__ void cp_wait() {
    asm volatile("cp.async.wait_group %0;" :: "n"(N) : "memory");
}

// ---------------- K_a: split W -> Whi/Wlo --------------------------------
__global__ void __launch_bounds__(256) wsplit_kernel(const float* __restrict__ W) {
    int i = (blockIdx.x * 256 + threadIdx.x) * 4;
    float4 v = *(const float4*)(W + i);
    __half2 h01 = __floats2half2_rn(v.x, v.y);
    __half2 h23 = __floats2half2_rn(v.z, v.w);
    float2 b01 = __half22float2(h01), b23 = __half22float2(h23);
    __half2 l01 = __floats2half2_rn(v.x - b01.x, v.y - b01.y);
    __half2 l23 = __floats2half2_rn(v.z - b23.x, v.w - b23.y);
    *(__half2*)(g_Whi + i)     = h01;
    *(__half2*)(g_Whi + i + 2) = h23;
    *(__half2*)(g_Wlo + i)     = l01;
    *(__half2*)(g_Wlo + i + 2) = l23;
}

// ---------------- K_a2: split h -> Ahi/Alo --------------------------------
__global__ void __launch_bounds__(256) asplit_kernel(const float* __restrict__ h) {
    size_t i = ((size_t)blockIdx.x * 256 + threadIdx.x) * 4;
    float4 v = *(const float4*)(h + i);
    __half2 h01 = __floats2half2_rn(v.x, v.y);
    __half2 h23 = __floats2half2_rn(v.z, v.w);
    float2 b01 = __half22float2(h01), b23 = __half22float2(h23);
    __half2 l01 = __floats2half2_rn(v.x - b01.x, v.y - b01.y);
    __half2 l23 = __floats2half2_rn(v.z - b23.x, v.w - b23.y);
    *(__half2*)(g_Ahi + i)     = h01;
    *(__half2*)(g_Ahi + i + 2) = h23;
    *(__half2*)(g_Alo + i)     = l01;
    *(__half2*)(g_Alo + i + 2) = l23;
}

// ---------------- K_b: uq = rs @ U^T; zero scores + matched --------------
__global__ void __launch_bounds__(256) init_kernel(const float* __restrict__ U,
                                                   const float* __restrict__ rs,
                                                   float* __restrict__ out) {
    int gtid = blockIdx.x * 256 + threadIdx.x;
    if (gtid < BB * SS) g_scores[gtid] = 0.0f;
    if (gtid < BB * DD) out[gtid] = 0.0f;

    int w = gtid >> 5;
    int lane = gtid & 31;
    if (w < BB * DD) {
        int b = w >> 10;
        int d = w & 1023;
        const float* Urow = U + (size_t)d * DD;
        const float* rb = rs + (size_t)b * DD;
        float acc = 0.0f;
        #pragma unroll 8
        for (int e = lane; e < DD; e += 32) acc += Urow[e] * rb[e];
        #pragma unroll
        for (int o = 16; o > 0; o >>= 1) acc += __shfl_xor_sync(0xffffffffu, acc, o);
        if (lane == 0) g_uq[w] = acc;
    }
}

// ---------------- K_c: fp16x3 GEMM + relu + score ------------------------
// TWO CTAs PER SM (anti-phase barriers cover each other's stage bubbles).
// CTA: 128 threads, tile 128m x 128n, BK=32, double-buffered cp.async.
// 4 warps = 2(m) x 2(n); warp tile 64m x 64n (optimal LDSM/MMA ratio).
#define LDH 40                    // halves per row slot; 80 B
#define ROWB (LDH * 2)            // 80 B
#define A_TILE_B (128 * ROWB)     // 10240 B per array
#define STAGE_B (4 * A_TILE_B)    // Ahi|Alo|Bhi|Blo = 40960 B
#define SMEM_DYN (2 * STAGE_B)    // 81920 B per CTA (2 CTAs = 160 KB/SM)
#define PST_B (32 * ROWB)         // dst displacement per piece: 2560 B
#define PST_H (32 * DD)           // src displacement per piece

// one 16B piece; `it` compile-time at call sites
__device__ __forceinline__ void cp_pc(int it, uint32_t dstA,
                                      const __half* sAhi, const __half* sAlo,
                                      const __half* sWhi, const __half* sWlo) {
    if (it < 4)
        cp16(dstA + it * PST_B, sAhi + (size_t)it * PST_H);
    else if (it < 8)
        cp16(dstA + A_TILE_B + (it - 4) * PST_B, sAlo + (size_t)(it - 4) * PST_H);
    else if (it < 12)
        cp16(dstA + 2 * A_TILE_B + (it - 8) * PST_B, sWhi + (size_t)(it - 8) * PST_H);
    else
        cp16(dstA + 3 * A_TILE_B + (it - 12) * PST_B, sWlo + (size_t)(it - 12) * PST_H);
}

__global__ void __launch_bounds__(128, 2) gemm_score_kernel(const float* __restrict__ rs) {
    extern __shared__ __align__(16) unsigned char dyn[];
    __shared__ float uqs[128], qs[128];

    const int tid = threadIdx.x;
    const int wid = tid >> 5;
    const int wm  = wid & 1;     // 2 m-warps (64 rows each)
    const int wn  = wid >> 1;    // 2 n-warps (64 cols each)
    const int m0  = blockIdx.y * 128;
    const int n0  = blockIdx.x * 128;
    const int b   = blockIdx.y >> 4;   // 16 m-blocks per batch

    uqs[tid] = g_uq[b * DD + n0 + tid];
    qs[tid]  = rs[(size_t)b * DD + n0 + tid];

    const uint32_t sbase = smem_u32(dyn);
    const int rowT = tid >> 2;                 // 0..31
    const int segT = tid & 3;                  // 0..3
    const uint32_t offT = rowT * ROWB + segT * 16;
    const __half* pAhi = g_Ahi + (size_t)(m0 + rowT) * DD + segT * 8;
    const __half* pAlo = g_Alo + (size_t)(m0 + rowT) * DD + segT * 8;
    const __half* pWhi = g_Whi + (size_t)(n0 + rowT) * DD + segT * 8;
    const __half* pWlo = g_Wlo + (size_t)(n0 + rowT) * DD + segT * 8;

    wmma::fragment<wmma::accumulator, 16, 16, 16, float> acc[4][4];
    #pragma unroll
    for (int i = 0; i < 4; i++)
        #pragma unroll
        for (int j = 0; j < 4; j++)
            wmma::fill_fragment(acc[i][j], 0.0f);

    // preload stage 0
    {
        const uint32_t d0 = sbase + offT;
        #pragma unroll
        for (int it = 0; it < 16; it++) cp_pc(it, d0, pAhi, pAlo, pWhi, pWlo);
        cp_commit();
    }

    #pragma unroll 1
    for (int s = 0; s < 32; s++) {
        cp_wait<0>();        // stage s landed
        __syncthreads();     // visible; buf (s+1)&1 reads all retired

        const __half* Ahi = (const __half*)(dyn + (s & 1) * STAGE_B);
        const __half* Bhi = Ahi + 2 * 128 * LDH;

        const int nk0 = (s + 1) * 32;
        const uint32_t ndst = sbase + ((s + 1) & 1) * STAGE_B + offT;
        const __half* nAhi = pAhi + nk0;
        const __half* nAlo = pAlo + nk0;
        const __half* nWhi = pWhi + nk0;
        const __half* nWlo = pWlo + nk0;
        const bool more = (s + 1 < 32);

        #pragma unroll
        for (int ks = 0; ks < 2; ks++) {
            wmma::fragment<wmma::matrix_b, 16, 16, 16, __half, wmma::col_major> bh[4], bl[4];
            #pragma unroll
            for (int j = 0; j < 4; j++) {
                const __half* pb = Bhi + (wn * 64 + j * 16) * LDH + ks * 16;
                wmma::load_matrix_sync(bh[j], pb, LDH);
                wmma::load_matrix_sync(bl[j], pb + 128 * LDH, LDH);
            }
            #pragma unroll
            for (int i = 0; i < 4; i++) {
                const int g = ks * 4 + i;           // group 0..7 (compile-time)
                if (more) {                          // 3,3,3,3,2,2 over g0..5
                    if (g < 4) {
                        cp_pc(3 * g,     ndst, nAhi, nAlo, nWhi, nWlo);
                        cp_pc(3 * g + 1, ndst, nAhi, nAlo, nWhi, nWlo);
                        cp_pc(3 * g + 2, ndst, nAhi, nAlo, nWhi, nWlo);
                    } else if (g < 6) {
                        cp_pc(12 + 2 * (g - 4), ndst, nAhi, nAlo, nWhi, nWlo);
                        cp_pc(13 + 2 * (g - 4), ndst, nAhi, nAlo, nWhi, nWlo);
                    }
                }
                wmma::fragment<wmma::matrix_a, 16, 16, 16, __half, wmma::row_major> ah, al;
                const __half* pa = Ahi + (wm * 64 + i * 16) * LDH + ks * 16;
                wmma::load_matrix_sync(ah, pa, LDH);
                wmma::load_matrix_sync(al, pa + 128 * LDH, LDH);
                #pragma unroll
                for (int j = 0; j < 4; j++)
                    wmma::mma_sync(acc[i][j], ah, bh[j], acc[i][j]);   // hi*hi
                #pragma unroll
                for (int j = 0; j < 4; j++)
                    wmma::mma_sync(acc[i][j], ah, bl[j], acc[i][j]);   // hi*lo
                #pragma unroll
                for (int j = 0; j < 4; j++)
                    wmma::mma_sync(acc[i][j], al, bh[j], acc[i][j]);   // lo*hi
                if (more && g == 5) cp_commit();    // all 16 issued; 2 groups slack
            }
        }
    }
    __syncthreads();   // all mma reads done before aliasing smem as Es

    // epilogue: stage acc to smem, relu(+uq)*q, row-reduce, atomicAdd
    float* Es = (float*)dyn;    // 128 x 132 fp32 = 67584 B (fits in 81920)
    #pragma unroll
    for (int i = 0; i < 4; i++)
        #pragma unroll
        for (int j = 0; j < 4; j++)
            wmma::store_matrix_sync(Es + (wm * 64 + i * 16) * 132 + (wn * 64 + j * 16),
                                    acc[i][j], 132, wmma::mem_row_major);
    __syncthreads();

    float partial = 0.0f;
    const float* row = Es + tid * 132;
    #pragma unroll 16
    for (int c = 0; c < 128; c++) {
        float v = row[c] + uqs[c];
        partial += fmaxf(v, 0.0f) * qs[c];
    }
    atomicAdd(&g_scores[m0 + tid], partial);
}

// ---------------- K_d: softmax over S per batch ---------------------------
__global__ void __launch_bounds__(256) softmax_kernel(float* __restrict__ out) {
    const int b = blockIdx.x;
    const int tid = threadIdx.x;
    __shared__ float red[256];
    const float* sc = g_scores + (size_t)b * SS;
    float* wout = out + BB * DD + (size_t)b * SS;

    float mx = -1e30f;
    for (int i = tid; i < SS; i += 256) mx = fmaxf(mx, sc[i]);
    red[tid] = mx; __syncthreads();
    for (int s = 128; s > 0; s >>= 1) {
        if (tid < s) red[tid] = fmaxf(red[tid], red[tid + s]);
        __syncthreads();
    }
    mx = red[0]; __syncthreads();

    float sum = 0.0f;
    for (int i = tid; i < SS; i += 256) {
        float e = expf(sc[i] - mx);
        wout[i] = e;
        sum += e;
    }
    red[tid] = sum; __syncthreads();
    for (int s = 128; s > 0; s >>= 1) {
        if (tid < s) red[tid] += red[tid + s];
        __syncthreads();
    }
    float inv = 1.0f / red[0];
    for (int i = tid; i < SS; i += 256) wout[i] *= inv;
}

// ---------------- K_e: matched[b,d] += sum_{s chunk} h*w (float4) --------
__global__ void __launch_bounds__(256) matched_kernel(const float* __restrict__ h,
                                                      float* __restrict__ out) {
    const int b  = blockIdx.y;
    const int sc = blockIdx.z;              // 8 chunks of 256 over S
    const int tid = threadIdx.x;            // 256 threads x 4 cols = 1024
    __shared__ float ws[256];
    ws[tid] = out[BB * DD + (size_t)b * SS + sc * 256 + tid];
    __syncthreads();

    const float4* hb = (const float4*)(h + ((size_t)b * SS + sc * 256) * DD) + tid;
    float4 acc = make_float4(0.f, 0.f, 0.f, 0.f);
    #pragma unroll 8
    for (int s = 0; s < 256; s++) {
        float4 v = hb[(size_t)s * (DD / 4)];
        float w = ws[s];
        acc.x += v.x * w; acc.y += v.y * w; acc.z += v.z * w; acc.w += v.w * w;
    }
    float* o = out + (size_t)b * DD + tid * 4;
    atomicAdd(o + 0, acc.x);
    atomicAdd(o + 1, acc.y);
    atomicAdd(o + 2, acc.z);
    atomicAdd(o + 3, acc.w);
}

// ---------------------------------------------------------------------------
extern "C" void kernel_launch(void* const* d_in, const int* in_sizes, int n_in,
                              void* d_out, int out_size) {
    const float* h  = (const float*)d_in[0];
    const float* rs = (const float*)d_in[1];
    const float* W  = (const float*)d_in[2];
    const float* U  = (const float*)d_in[3];
    float* out = (float*)d_out;

    cudaFuncSetAttribute(gemm_score_kernel,
                         cudaFuncAttributeMaxDynamicSharedMemorySize, SMEM_DYN);

    wsplit_kernel<<<1024, 256>>>(W);
    asplit_kernel<<<65536, 256>>>(h);
    init_kernel<<<4096, 256>>>(U, rs, out);
    gemm_score_kernel<<<dim3(8, 512), 128, SMEM_DYN>>>(rs);
    softmax_kernel<<<BB, 256>>>(out);
    matched_kernel<<<dim3(1, BB, 8), 256>>>(h, out);
}

// round 14
// speedup vs baseline: 1.2716x; 1.0432x over previous
#include <cuda_runtime.h>
#include <cuda_fp16.h>
#include <mma.h>
#include <cstdint>

using namespace nvcuda;

#define BB 32
#define SS 2048
#define DD 1024
#define MM (BB * SS)

// ---------------- scratch (static device globals; no runtime alloc) ------
__device__ float  g_scores[BB * SS];
__device__ float  g_uq[BB * DD];
__device__ __half g_Whi[DD * DD];
__device__ __half g_Wlo[DD * DD];          // unscaled residual (subnormals ok)

// ---------------- cp.async helpers ---------------------------------------
__device__ __forceinline__ uint32_t smem_u32(const void* p) {
    uint32_t a;
    asm("{ .reg .u64 t; cvta.to.shared.u64 t, %1; cvt.u32.u64 %0, t; }"
        : "=r"(a) : "l"(p));
    return a;
}
__device__ __forceinline__ void cp16(uint32_t dst, const void* src) {
    asm volatile("cp.async.cg.shared.global [%0], [%1], 16;" :: "r"(dst), "l"(src) : "memory");
}
__device__ __forceinline__ void cp_commit() {
    asm volatile("cp.async.commit_group;" ::: "memory");
}
template <int N> __device__ __forceinline__ void cp_wait() {
    asm volatile("cp.async.wait_group %0;" :: "n"(N) : "memory");
}

// ---------------- K_a: split W -> Whi/Wlo --------------------------------
__global__ void __launch_bounds__(256) wsplit_kernel(const float* __restrict__ W) {
    int i = (blockIdx.x * 256 + threadIdx.x) * 4;
    float4 v = *(const float4*)(W + i);
    __half2 h01 = __floats2half2_rn(v.x, v.y);
    __half2 h23 = __floats2half2_rn(v.z, v.w);
    float2 b01 = __half22float2(h01), b23 = __half22float2(h23);
    __half2 l01 = __floats2half2_rn(v.x - b01.x, v.y - b01.y);
    __half2 l23 = __floats2half2_rn(v.z - b23.x, v.w - b23.y);
    *(__half2*)(g_Whi + i)     = h01;
    *(__half2*)(g_Whi + i + 2) = h23;
    *(__half2*)(g_Wlo + i)     = l01;
    *(__half2*)(g_Wlo + i + 2) = l23;
}

// ---------------- K_b: uq = rs @ U^T; zero scores + matched --------------
__global__ void __launch_bounds__(256) init_kernel(const float* __restrict__ U,
                                                   const float* __restrict__ rs,
                                                   float* __restrict__ out) {
    int gtid = blockIdx.x * 256 + threadIdx.x;
    if (gtid < BB * SS) g_scores[gtid] = 0.0f;
    if (gtid < BB * DD) out[gtid] = 0.0f;

    int w = gtid >> 5;
    int lane = gtid & 31;
    if (w < BB * DD) {
        int b = w >> 10;
        int d = w & 1023;
        const float* Urow = U + (size_t)d * DD;
        const float* rb = rs + (size_t)b * DD;
        float acc = 0.0f;
        #pragma unroll 8
        for (int e = lane; e < DD; e += 32) acc += Urow[e] * rb[e];
        #pragma unroll
        for (int o = 16; o > 0; o >>= 1) acc += __shfl_xor_sync(0xffffffffu, acc, o);
        if (lane == 0) g_uq[w] = acc;
    }
}

// ---------------- K_c: fp16x3 GEMM + relu + score ------------------------
// TWO CTAs PER SM. CTA: 128 threads, tile 128m x 128n, BK=32, double-buffered.
// 4 warps = 2(m) x 2(n); warp tile 64m x 64n.
// A loaded fp32 and split hi/lo in-kernel. Schedule:
//   g0: LDG A pieces 0-3      g4: LDG A pieces 4-7
//   g1: cp_b 0,1              g5: cp_b 4,5
//   g2: cp_b 2,3              g6: cp_b 6,7 + commit
//   g3: STS A pieces 0-3      g7: STS A pieces 4-7
#define LDH 40                    // halves per row slot; 80 B
#define ROWB (LDH * 2)            // 80 B
#define A_TILE_B (128 * ROWB)     // 10240 B per array
#define STAGE_B (4 * A_TILE_B)    // Ahi|Alo|Bhi|Blo = 40960 B
#define SMEM_DYN (2 * STAGE_B)    // 81920 B per CTA
#define BPST_B (32 * ROWB)        // B dst displacement per piece
#define BPST_H (32 * DD)          // B src displacement per piece

// one 16B B piece; p in [0,8): 0-3 = Whi, 4-7 = Wlo (compile-time)
__device__ __forceinline__ void cp_b(int p, uint32_t dstA,
                                     const __half* sWhi, const __half* sWlo) {
    if (p < 4)
        cp16(dstA + 2 * A_TILE_B + p * BPST_B, sWhi + (size_t)p * BPST_H);
    else
        cp16(dstA + 3 * A_TILE_B + (p - 4) * BPST_B, sWlo + (size_t)(p - 4) * BPST_H);
}

// convert one float4 -> 4 hi halves + 4 lo halves, store to smem
__device__ __forceinline__ void cvt_sts(float4 v, unsigned char* smemc, uint32_t off) {
    __half2 hA = __floats2half2_rn(v.x, v.y);
    __half2 hB = __floats2half2_rn(v.z, v.w);
    float2 fA = __half22float2(hA), fB = __half22float2(hB);
    __half2 lA = __floats2half2_rn(v.x - fA.x, v.y - fA.y);
    __half2 lB = __floats2half2_rn(v.z - fB.x, v.w - fB.y);
    uint2 hv, lv;
    hv.x = *reinterpret_cast<uint32_t*>(&hA);
    hv.y = *reinterpret_cast<uint32_t*>(&hB);
    lv.x = *reinterpret_cast<uint32_t*>(&lA);
    lv.y = *reinterpret_cast<uint32_t*>(&lB);
    *(uint2*)(smemc + off)            = hv;
    *(uint2*)(smemc + off + A_TILE_B) = lv;
}

__global__ void __launch_bounds__(128, 2) gemm_score_kernel(const float* __restrict__ h,
                                                            const float* __restrict__ rs) {
    extern __shared__ __align__(16) unsigned char dyn[];
    __shared__ float uqs[128], qs[128];

    const int tid = threadIdx.x;
    const int wid = tid >> 5;
    const int wm  = wid & 1;     // 2 m-warps (64 rows each)
    const int wn  = wid >> 1;    // 2 n-warps (64 cols each)
    const int m0  = blockIdx.y * 128;
    const int n0  = blockIdx.x * 128;
    const int b   = blockIdx.y >> 4;   // 16 m-blocks per batch

    uqs[tid] = g_uq[b * DD + n0 + tid];
    qs[tid]  = rs[(size_t)b * DD + n0 + tid];

    const uint32_t sbase = smem_u32(dyn);

    // A fp32 addressing: piece i covers rows i*16 + (tid>>3), 8 thread-cols
    const int arow = tid >> 3;                  // 0..15
    const int acol = (tid & 7) * 4;             // float col, 0..28
    const float* pA = h + (size_t)(m0 + arow) * DD + acol;
    const uint32_t aoff = arow * ROWB + acol * 2;    // smem byte offset (hi)

    // B addressing: piece p covers rows p*32 + (tid>>2), 4 thread-segs
    const int brow = tid >> 2;                  // 0..31
    const int bseg = tid & 3;                   // 0..3
    const __half* pWhi = g_Whi + (size_t)(n0 + brow) * DD + bseg * 8;
    const __half* pWlo = g_Wlo + (size_t)(n0 + brow) * DD + bseg * 8;
    const uint32_t boff = brow * ROWB + bseg * 16;

    wmma::fragment<wmma::accumulator, 16, 16, 16, float> acc[4][4];
    #pragma unroll
    for (int i = 0; i < 4; i++)
        #pragma unroll
        for (int j = 0; j < 4; j++)
            wmma::fill_fragment(acc[i][j], 0.0f);

    // prologue: stage 0 (A direct, B cp.async)
    {
        unsigned char* smemc = dyn;
        #pragma unroll
        for (int i = 0; i < 8; i++) {
            float4 v = *(const float4*)(pA + (size_t)(i * 16) * DD);
            cvt_sts(v, smemc, aoff + i * 16 * ROWB);
        }
        const uint32_t d0 = sbase + boff;
        #pragma unroll
        for (int p = 0; p < 8; p++) cp_b(p, d0, pWhi, pWlo);
        cp_commit();
    }

    #pragma unroll 1
    for (int s = 0; s < 32; s++) {
        cp_wait<0>();        // stage s B landed
        __syncthreads();     // stage s visible (BAR drains A STS); buf (s+1)&1 free

        const __half* Ahi = (const __half*)(dyn + (s & 1) * STAGE_B);
        const __half* Bhi = Ahi + 2 * 128 * LDH;

        const int nk0 = (s + 1) * 32;
        unsigned char* nsm = dyn + ((s + 1) & 1) * STAGE_B;
        const uint32_t ndst = sbase + ((s + 1) & 1) * STAGE_B + boff;
        const float* nA = pA + nk0;
        const __half* nWhi = pWhi + nk0;
        const __half* nWlo = pWlo + nk0;
        const bool more = (s + 1 < 32);

        float4 av[4];    // A prefetch staging; generation stored before reuse

        #pragma unroll
        for (int ks = 0; ks < 2; ks++) {
            wmma::fragment<wmma::matrix_b, 16, 16, 16, __half, wmma::col_major> bh[4], bl[4];
            #pragma unroll
            for (int j = 0; j < 4; j++) {
                const __half* pb = Bhi + (wn * 64 + j * 16) * LDH + ks * 16;
                wmma::load_matrix_sync(bh[j], pb, LDH);
                wmma::load_matrix_sync(bl[j], pb + 128 * LDH, LDH);
            }
            #pragma unroll
            for (int i = 0; i < 4; i++) {
                const int g = ks * 4 + i;           // group 0..7 (compile-time)
                if (more) {
                    if (g == 0 || g == 4) {         // LDG A pieces 0-3 / 4-7
                        const int base = (g == 0) ? 0 : 4;
                        #pragma unroll
                        for (int q = 0; q < 4; q++)
                            av[q] = *(const float4*)(nA + (size_t)((base + q) * 16) * DD);
                    } else if (g == 1 || g == 2 || g == 5 || g == 6) {
                        const int p = (g <= 2) ? (g - 1) * 2 : (g - 3) * 2;  // 0,2,4,6
                        cp_b(p,     ndst, nWhi, nWlo);
                        cp_b(p + 1, ndst, nWhi, nWlo);
                        if (g == 6) cp_commit();
                    } else {                         // g == 3, 7: STS the loaded gen
                        const int base = (g == 3) ? 0 : 4;
                        #pragma unroll
                        for (int q = 0; q < 4; q++)
                            cvt_sts(av[q], nsm, aoff + (base + q) * 16 * ROWB);
                    }
                }
                wmma::fragment<wmma::matrix_a, 16, 16, 16, __half, wmma::row_major> ah, al;
                const __half* pa = Ahi + (wm * 64 + i * 16) * LDH + ks * 16;
                wmma::load_matrix_sync(ah, pa, LDH);
                wmma::load_matrix_sync(al, pa + 128 * LDH, LDH);
                #pragma unroll
                for (int j = 0; j < 4; j++)
                    wmma::mma_sync(acc[i][j], ah, bh[j], acc[i][j]);   // hi*hi
                #pragma unroll
                for (int j = 0; j < 4; j++)
                    wmma::mma_sync(acc[i][j], ah, bl[j], acc[i][j]);   // hi*lo
                #pragma unroll
                for (int j = 0; j < 4; j++)
                    wmma::mma_sync(acc[i][j], al, bh[j], acc[i][j]);   // lo*hi
            }
        }
    }
    __syncthreads();   // all mma reads done before aliasing smem as Es

    // epilogue: stage acc to smem, relu(+uq)*q, row-reduce, atomicAdd
    float* Es = (float*)dyn;    // 128 x 132 fp32 = 67584 B
    #pragma unroll
    for (int i = 0; i < 4; i++)
        #pragma unroll
        for (int j = 0; j < 4; j++)
            wmma::store_matrix_sync(Es + (wm * 64 + i * 16) * 132 + (wn * 64 + j * 16),
                                    acc[i][j], 132, wmma::mem_row_major);
    __syncthreads();

    float partial = 0.0f;
    const float* row = Es + tid * 132;
    #pragma unroll 16
    for (int c = 0; c < 128; c++) {
        float v = row[c] + uqs[c];
        partial += fmaxf(v, 0.0f) * qs[c];
    }
    atomicAdd(&g_scores[m0 + tid], partial);
}

// ---------------- K_d: softmax over S per batch ---------------------------
__global__ void __launch_bounds__(256) softmax_kernel(float* __restrict__ out) {
    const int b = blockIdx.x;
    const int tid = threadIdx.x;
    __shared__ float red[256];
    const float* sc = g_scores + (size_t)b * SS;
    float* wout = out + BB * DD + (size_t)b * SS;

    float mx = -1e30f;
    for (int i = tid; i < SS; i += 256) mx = fmaxf(mx, sc[i]);
    red[tid] = mx; __syncthreads();
    for (int s = 128; s > 0; s >>= 1) {
        if (tid < s) red[tid] = fmaxf(red[tid], red[tid + s]);
        __syncthreads();
    }
    mx = red[0]; __syncthreads();

    float sum = 0.0f;
    for (int i = tid; i < SS; i += 256) {
        float e = expf(sc[i] - mx);
        wout[i] = e;
        sum += e;
    }
    red[tid] = sum; __syncthreads();
    for (int s = 128; s > 0; s >>= 1) {
        if (tid < s) red[tid] += red[tid + s];
        __syncthreads();
    }
    float inv = 1.0f / red[0];
    for (int i = tid; i < SS; i += 256) wout[i] *= inv;
}

// ---------------- K_e: matched[b,d] += sum_{s chunk} h*w (float4) --------
__global__ void __launch_bounds__(256) matched_kernel(const float* __restrict__ h,
                                                      float* __restrict__ out) {
    const int b  = blockIdx.y;
    const int sc = blockIdx.z;              // 16 chunks of 128 over S
    const int tid = threadIdx.x;            // 256 threads x 4 cols = 1024
    __shared__ float ws[128];
    if (tid < 128) ws[tid] = out[BB * DD + (size_t)b * SS + sc * 128 + tid];
    __syncthreads();

    const float4* hb = (const float4*)(h + ((size_t)b * SS + sc * 128) * DD) + tid;
    float4 acc = make_float4(0.f, 0.f, 0.f, 0.f);
    #pragma unroll 8
    for (int s = 0; s < 128; s++) {
        float4 v = hb[(size_t)s * (DD / 4)];
        float w = ws[s];
        acc.x += v.x * w; acc.y += v.y * w; acc.z += v.z * w; acc.w += v.w * w;
    }
    float* o = out + (size_t)b * DD + tid * 4;
    atomicAdd(o + 0, acc.x);
    atomicAdd(o + 1, acc.y);
    atomicAdd(o + 2, acc.z);
    atomicAdd(o + 3, acc.w);
}

// ---------------------------------------------------------------------------
extern "C" void kernel_launch(void* const* d_in, const int* in_sizes, int n_in,
                              void* d_out, int out_size) {
    const float* h  = (const float*)d_in[0];
    const float* rs = (const float*)d_in[1];
    const float* W  = (const float*)d_in[2];
    const float* U  = (const float*)d_in[3];
    float* out = (float*)d_out;

    cudaFuncSetAttribute(gemm_score_kernel,
                         cudaFuncAttributeMaxDynamicSharedMemorySize, SMEM_DYN);

    wsplit_kernel<<<1024, 256>>>(W);
    init_kernel<<<4096, 256>>>(U, rs, out);
    gemm_score_kernel<<<dim3(8, 512), 128, SMEM_DYN>>>(h, rs);
    softmax_kernel<<<BB, 256>>>(out);
    matched_kernel<<<dim3(1, BB, 16), 256>>>(h, out);
}